// round 1
// baseline (speedup 1.0000x reference)
#include <cuda_runtime.h>
#include <cfloat>

#define BB 8
#define CC 64
#define NN 4096
#define OO 64
#define KNB 20

// Scratch (device globals: allocation-free per harness rules)
__device__ float g_pd[134217728];   // [B*N, N] pairwise "distance" (negative sq dist), 537MB
__device__ float g_sq[32768];       // [B*N] squared norms
__device__ float g_P[2097152];      // [B*N, O]  x·(W1-W2)^T
__device__ float g_Q[2097152];      // [B*N, O]  x·W2^T

// ---------------------------------------------------------------------------
// Kernel 1: squared norms. sq[b,n] = sum_c x[b,c,n]^2 (same FMA order as GEMM)
// ---------------------------------------------------------------------------
__global__ void sq_kernel(const float* __restrict__ x) {
    int t = blockIdx.x * blockDim.x + threadIdx.x;   // 0..32767
    int b = t >> 12, n = t & 4095;
    const float* xp = x + (size_t)b * CC * NN + n;
    float s = 0.f;
    #pragma unroll
    for (int c = 0; c < CC; ++c) {
        float v = xp[(size_t)c * NN];
        s = fmaf(v, v, s);
    }
    g_sq[t] = s;
}

// ---------------------------------------------------------------------------
// Kernel 2: P = x·(W1-W2)^T, Q = x·W2^T   (collapses the edge GEMM)
// block: 256 threads = 4 points x 64 outputs
// ---------------------------------------------------------------------------
__global__ __launch_bounds__(256) void pq_kernel(const float* __restrict__ x,
                                                 const float* __restrict__ W) {
    __shared__ float Wa[CC][OO + 1];   // (W1-W2) transposed [c][o], padded
    __shared__ float Wb[CC][OO + 1];   // W2 transposed
    __shared__ float xs[CC][4];
    int tid = threadIdx.x;
    #pragma unroll
    for (int i = 0; i < 16; ++i) {
        int fid = tid + i * 256;       // 0..4095 over (o,c)
        int o = fid >> 6, c = fid & 63;
        float w1 = W[o * 128 + c];
        float w2 = W[o * 128 + 64 + c];
        Wa[c][o] = w1 - w2;
        Wb[c][o] = w2;
    }
    int nbase = blockIdx.x * 4;        // global point index base (b*4096+n)
    int b = nbase >> 12;
    int nb = nbase & 4095;
    {
        int c = tid >> 2, j = tid & 3;
        xs[c][j] = x[(size_t)b * CC * NN + (size_t)c * NN + nb + j];
    }
    __syncthreads();
    int o = tid & 63, nl = tid >> 6;
    float p = 0.f, q = 0.f;
    #pragma unroll
    for (int c = 0; c < CC; ++c) {
        float xv = xs[c][nl];
        p = fmaf(xv, Wa[c][o], p);
        q = fmaf(xv, Wb[c][o], q);
    }
    size_t g = (size_t)(nbase + nl);
    g_P[g * OO + o] = p;
    g_Q[g * OO + o] = q;
}

// ---------------------------------------------------------------------------
// Kernel 3: pd GEMM.  pd[b,n,m] = 2*sum_c x[c,n]x[c,m] - sq[n] - sq[m]
// 128x128 tile, 256 threads, 8x8 microtile, full K=64 in smem.
// ---------------------------------------------------------------------------
__global__ __launch_bounds__(256) void pd_gemm(const float* __restrict__ x) {
    __shared__ float As[CC][128];
    __shared__ float Bs[CC][128];
    __shared__ float sqn[128], sqm[128];

    int b = blockIdx.z;
    int n0 = blockIdx.y * 128, m0 = blockIdx.x * 128;
    const float* xb = x + (size_t)b * CC * NN;
    int tid = threadIdx.x;

    #pragma unroll
    for (int i = 0; i < 8; ++i) {
        int fid = tid + i * 256;          // float4 id 0..2047
        int c = fid >> 5, v = (fid & 31) << 2;
        *(float4*)&As[c][v] = *(const float4*)&xb[(size_t)c * NN + n0 + v];
        *(float4*)&Bs[c][v] = *(const float4*)&xb[(size_t)c * NN + m0 + v];
    }
    if (tid < 128)       sqn[tid]       = g_sq[b * NN + n0 + tid];
    else                 sqm[tid - 128] = g_sq[b * NN + m0 + (tid - 128)];
    __syncthreads();

    int tx = tid & 15, ty = tid >> 4;
    float acc[8][8];
    #pragma unroll
    for (int i = 0; i < 8; ++i)
        #pragma unroll
        for (int j = 0; j < 8; ++j) acc[i][j] = 0.f;

    #pragma unroll 4
    for (int c = 0; c < CC; ++c) {
        float ar[8], br[8];
        *(float4*)&ar[0] = *(float4*)&As[c][ty * 8];
        *(float4*)&ar[4] = *(float4*)&As[c][ty * 8 + 4];
        *(float4*)&br[0] = *(float4*)&Bs[c][tx * 8];
        *(float4*)&br[4] = *(float4*)&Bs[c][tx * 8 + 4];
        #pragma unroll
        for (int i = 0; i < 8; ++i)
            #pragma unroll
            for (int j = 0; j < 8; ++j)
                acc[i][j] = fmaf(ar[i], br[j], acc[i][j]);
    }

    float* outp = g_pd + ((size_t)(b * NN + n0)) * NN + m0;
    #pragma unroll
    for (int i = 0; i < 8; ++i) {
        int r = ty * 8 + i;
        float sn = sqn[r];
        float res[8];
        #pragma unroll
        for (int j = 0; j < 8; ++j)
            res[j] = 2.f * acc[i][j] - sn - sqm[tx * 8 + j];
        *(float4*)&outp[(size_t)r * NN + tx * 8]     = *(float4*)&res[0];
        *(float4*)&outp[(size_t)r * NN + tx * 8 + 4] = *(float4*)&res[4];
    }
}

// ---------------------------------------------------------------------------
// Kernel 4: per-row top-20 (thread-per-row, min-replace list) fused with
// gather + BN affine + leaky-relu + max-over-k + transposed store.
// ---------------------------------------------------------------------------
__global__ __launch_bounds__(128) void topk_out_kernel(
    const float* __restrict__ gamma, const float* __restrict__ beta,
    const float* __restrict__ rmean, const float* __restrict__ rvar,
    float* __restrict__ out)
{
    __shared__ float s_scale[OO], s_bias[OO];
    int tid = threadIdx.x;
    if (tid < OO) {
        float sc = gamma[tid] * rsqrtf(rvar[tid] + 1e-5f);
        s_scale[tid] = sc;
        s_bias[tid]  = beta[tid] - rmean[tid] * sc;
    }
    __syncthreads();

    int t = blockIdx.x * 128 + tid;   // global row 0..32767
    int b = t >> 12, n = t & 4095;

    const float4* row = (const float4*)(g_pd + (size_t)t * NN);
    float vals[KNB];
    int   idxs[KNB];
    #pragma unroll
    for (int i = 0; i < KNB; ++i) { vals[i] = -FLT_MAX; idxs[i] = 0; }
    float vmin = -FLT_MAX;
    int   vminpos = 0;

    #pragma unroll 4
    for (int i = 0; i < NN / 4; ++i) {
        float4 v4 = row[i];
        float vv[4] = {v4.x, v4.y, v4.z, v4.w};
        #pragma unroll
        for (int j = 0; j < 4; ++j) {
            float v = vv[j];
            if (v > vmin) {           // strict '>' keeps lowest index on ties (JAX stable)
                vals[vminpos] = v;
                idxs[vminpos] = i * 4 + j;
                vmin = vals[0]; vminpos = 0;
                #pragma unroll
                for (int s = 1; s < KNB; ++s)
                    if (vals[s] < vmin) { vmin = vals[s]; vminpos = s; }
            }
        }
    }

    const float* Pp   = g_P + (size_t)t * OO;
    const float* Qb   = g_Q + (size_t)b * NN * OO;
    float*       outb = out + (size_t)b * OO * NN + n;

    #pragma unroll
    for (int oc = 0; oc < OO; oc += 16) {
        float pr[16], best[16];
        #pragma unroll
        for (int j4 = 0; j4 < 4; ++j4)
            *(float4*)&pr[j4 * 4] = *(const float4*)&Pp[oc + j4 * 4];
        #pragma unroll
        for (int j = 0; j < 16; ++j) best[j] = -FLT_MAX;

        for (int k = 0; k < KNB; ++k) {
            const float* Qr = Qb + (size_t)idxs[k] * OO + oc;
            float qv[16];
            #pragma unroll
            for (int j4 = 0; j4 < 4; ++j4)
                *(float4*)&qv[j4 * 4] = __ldg((const float4*)&Qr[j4 * 4]);
            #pragma unroll
            for (int j = 0; j < 16; ++j) {
                float y = (pr[j] + qv[j]) * s_scale[oc + j] + s_bias[oc + j];
                y = (y >= 0.f) ? y : 0.2f * y;
                best[j] = fmaxf(best[j], y);
            }
        }
        #pragma unroll
        for (int j = 0; j < 16; ++j)
            outb[(size_t)(oc + j) * NN] = best[j];
    }
}

// ---------------------------------------------------------------------------
extern "C" void kernel_launch(void* const* d_in, const int* in_sizes, int n_in,
                              void* d_out, int out_size) {
    const float* x     = (const float*)d_in[0];
    const float* W     = (const float*)d_in[1];
    const float* gamma = (const float*)d_in[2];
    const float* beta  = (const float*)d_in[3];
    const float* rmean = (const float*)d_in[4];
    const float* rvar  = (const float*)d_in[5];
    float* out = (float*)d_out;

    sq_kernel<<<128, 256>>>(x);
    pq_kernel<<<8192, 256>>>(x, W);
    {
        dim3 grid(NN / 128, NN / 128, BB);
        pd_gemm<<<grid, 256>>>(x);
    }
    topk_out_kernel<<<256, 128>>>(gamma, beta, rmean, rvar, out);
}

// round 2
// speedup vs baseline: 2.0202x; 2.0202x over previous
#include <cuda_runtime.h>
#include <cfloat>

#define BB 8
#define CC 64
#define NN 4096
#define OO 64
#define KNB 20
#define FULLMASK 0xffffffffu

// Scratch (device globals: allocation-free per harness rules)
__device__ float g_pd[134217728];   // [B*N, N] pairwise "distance", 537MB
__device__ float g_sq[32768];       // [B*N] squared norms
__device__ float g_P[2097152];      // [B*N, O]  x·(W1-W2)^T
__device__ float g_Q[2097152];      // [B*N, O]  x·W2^T

// ---------------------------------------------------------------------------
// Kernel 1: squared norms. sq[b,n] = sum_c x[b,c,n]^2 (same FMA order as GEMM)
// ---------------------------------------------------------------------------
__global__ void sq_kernel(const float* __restrict__ x) {
    int t = blockIdx.x * blockDim.x + threadIdx.x;   // 0..32767
    int b = t >> 12, n = t & 4095;
    const float* xp = x + (size_t)b * CC * NN + n;
    float s = 0.f;
    #pragma unroll
    for (int c = 0; c < CC; ++c) {
        float v = xp[(size_t)c * NN];
        s = fmaf(v, v, s);
    }
    g_sq[t] = s;
}

// ---------------------------------------------------------------------------
// Kernel 2: P = x·(W1-W2)^T, Q = x·W2^T   (collapses the edge GEMM)
// ---------------------------------------------------------------------------
__global__ __launch_bounds__(256) void pq_kernel(const float* __restrict__ x,
                                                 const float* __restrict__ W) {
    __shared__ float Wa[CC][OO + 1];
    __shared__ float Wb[CC][OO + 1];
    __shared__ float xs[CC][4];
    int tid = threadIdx.x;
    #pragma unroll
    for (int i = 0; i < 16; ++i) {
        int fid = tid + i * 256;
        int o = fid >> 6, c = fid & 63;
        float w1 = W[o * 128 + c];
        float w2 = W[o * 128 + 64 + c];
        Wa[c][o] = w1 - w2;
        Wb[c][o] = w2;
    }
    int nbase = blockIdx.x * 4;
    int b = nbase >> 12;
    int nb = nbase & 4095;
    {
        int c = tid >> 2, j = tid & 3;
        xs[c][j] = x[(size_t)b * CC * NN + (size_t)c * NN + nb + j];
    }
    __syncthreads();
    int o = tid & 63, nl = tid >> 6;
    float p = 0.f, q = 0.f;
    #pragma unroll
    for (int c = 0; c < CC; ++c) {
        float xv = xs[c][nl];
        p = fmaf(xv, Wa[c][o], p);
        q = fmaf(xv, Wb[c][o], q);
    }
    size_t g = (size_t)(nbase + nl);
    g_P[g * OO + o] = p;
    g_Q[g * OO + o] = q;
}

// ---------------------------------------------------------------------------
// Kernel 3: symmetric pd GEMM. Only tiles with nt <= mt computed; the
// transposed tile is mirror-stored. pd[n][m] = 2*x_n·x_m - sq[n] - sq[m].
// ---------------------------------------------------------------------------
__global__ __launch_bounds__(256) void pd_gemm_sym(const float* __restrict__ x) {
    int mt = blockIdx.x, nt = blockIdx.y;
    if (nt > mt) return;                         // upper triangle only

    __shared__ float As[CC][128];
    __shared__ float Bs[CC][128];
    __shared__ float sqn[128], sqm[128];

    int b = blockIdx.z;
    int n0 = nt * 128, m0 = mt * 128;
    const float* xb = x + (size_t)b * CC * NN;
    int tid = threadIdx.x;

    #pragma unroll
    for (int i = 0; i < 8; ++i) {
        int fid = tid + i * 256;
        int c = fid >> 5, v = (fid & 31) << 2;
        *(float4*)&As[c][v] = *(const float4*)&xb[(size_t)c * NN + n0 + v];
        *(float4*)&Bs[c][v] = *(const float4*)&xb[(size_t)c * NN + m0 + v];
    }
    if (tid < 128)       sqn[tid]       = g_sq[b * NN + n0 + tid];
    else                 sqm[tid - 128] = g_sq[b * NN + m0 + (tid - 128)];
    __syncthreads();

    int tx = tid & 15, ty = tid >> 4;
    float acc[8][8];
    #pragma unroll
    for (int i = 0; i < 8; ++i)
        #pragma unroll
        for (int j = 0; j < 8; ++j) acc[i][j] = 0.f;

    #pragma unroll 4
    for (int c = 0; c < CC; ++c) {
        float ar[8], br[8];
        *(float4*)&ar[0] = *(float4*)&As[c][ty * 8];
        *(float4*)&ar[4] = *(float4*)&As[c][ty * 8 + 4];
        *(float4*)&br[0] = *(float4*)&Bs[c][tx * 8];
        *(float4*)&br[4] = *(float4*)&Bs[c][tx * 8 + 4];
        #pragma unroll
        for (int i = 0; i < 8; ++i)
            #pragma unroll
            for (int j = 0; j < 8; ++j)
                acc[i][j] = fmaf(ar[i], br[j], acc[i][j]);
    }

    // normal store: tile [n0.., m0..]
    float* outp = g_pd + ((size_t)(b * NN + n0)) * NN + m0;
    #pragma unroll
    for (int i = 0; i < 8; ++i) {
        int r = ty * 8 + i;
        float sn = sqn[r];
        float res[8];
        #pragma unroll
        for (int j = 0; j < 8; ++j)
            res[j] = 2.f * acc[i][j] - sn - sqm[tx * 8 + j];
        *(float4*)&outp[(size_t)r * NN + tx * 8]     = *(float4*)&res[0];
        *(float4*)&outp[(size_t)r * NN + tx * 8 + 4] = *(float4*)&res[4];
    }

    // mirror store: tile [m0.., n0..] (skip on diagonal)
    if (nt != mt) {
        float* outq = g_pd + ((size_t)(b * NN + m0)) * NN + n0;
        #pragma unroll
        for (int j = 0; j < 8; ++j) {
            int rm = tx * 8 + j;
            float sm = sqm[rm];
            float4 lo, hi;
            lo.x = 2.f * acc[0][j] - sqn[ty * 8 + 0] - sm;
            lo.y = 2.f * acc[1][j] - sqn[ty * 8 + 1] - sm;
            lo.z = 2.f * acc[2][j] - sqn[ty * 8 + 2] - sm;
            lo.w = 2.f * acc[3][j] - sqn[ty * 8 + 3] - sm;
            hi.x = 2.f * acc[4][j] - sqn[ty * 8 + 4] - sm;
            hi.y = 2.f * acc[5][j] - sqn[ty * 8 + 5] - sm;
            hi.z = 2.f * acc[6][j] - sqn[ty * 8 + 6] - sm;
            hi.w = 2.f * acc[7][j] - sqn[ty * 8 + 7] - sm;
            *(float4*)&outq[(size_t)rm * NN + ty * 8]     = lo;
            *(float4*)&outq[(size_t)rm * NN + ty * 8 + 4] = hi;
        }
    }
}

// ---------------------------------------------------------------------------
// Kernel 4: warp-per-row top-20 (warp-cooperative, lane-distributed list)
// fused with gather + BN affine + leaky-relu + max-over-k + transposed store.
// ---------------------------------------------------------------------------
__global__ __launch_bounds__(256) void topk_fused(
    const float* __restrict__ gamma, const float* __restrict__ beta,
    const float* __restrict__ rmean, const float* __restrict__ rvar,
    float* __restrict__ out)
{
    int warp = threadIdx.x >> 5, lane = threadIdx.x & 31;
    int row = blockIdx.x * 8 + warp;        // 0..32767
    int b = row >> 12, n = row & 4095;

    const float4* rowp = (const float4*)(g_pd + (size_t)row * NN);

    // lane-distributed top-20: lanes 0..19 each hold one (val, idx) slot
    float lv = -FLT_MAX;
    int   li = 0;
    float vmin = -FLT_MAX;   // uniform across warp
    int   minpos = 0;        // uniform across warp

    float4 cur = __ldcs(&rowp[lane]);
    for (int it = 0; it < 32; ++it) {
        float4 nxt = cur;
        if (it < 31) nxt = __ldcs(&rowp[(it + 1) * 32 + lane]);
        int ibase = (it * 32 + lane) * 4;
        #pragma unroll
        for (int j = 0; j < 4; ++j) {
            float v = (j == 0) ? cur.x : (j == 1) ? cur.y : (j == 2) ? cur.z : cur.w;
            unsigned m = __ballot_sync(FULLMASK, v > vmin);
            while (m) {
                int lead = __ffs(m) - 1;
                float cv = __shfl_sync(FULLMASK, v, lead);
                int   ci = __shfl_sync(FULLMASK, ibase, lead) + j;
                if (lane == minpos) { lv = cv; li = ci; }
                // recompute warp-uniform (vmin, minpos)
                float t = (lane < KNB) ? lv : FLT_MAX;
                #pragma unroll
                for (int off = 16; off; off >>= 1)
                    t = fminf(t, __shfl_xor_sync(FULLMASK, t, off));
                vmin = t;
                minpos = __ffs(__ballot_sync(FULLMASK, lane < KNB && lv == vmin)) - 1;
                m &= ~(1u << lead);
                m &= __ballot_sync(FULLMASK, v > vmin);
            }
        }
        cur = nxt;
    }

    // ---- fused epilogue: out[b,o,n] = max_k leaky(BN(P[row,o] + Q[idx_k,o]))
    float sc1 = gamma[lane]      * rsqrtf(rvar[lane]      + 1e-5f);
    float sc2 = gamma[lane + 32] * rsqrtf(rvar[lane + 32] + 1e-5f);
    float bi1 = beta[lane]      - rmean[lane]      * sc1;
    float bi2 = beta[lane + 32] - rmean[lane + 32] * sc2;
    float p1 = g_P[(size_t)row * OO + lane];
    float p2 = g_P[(size_t)row * OO + lane + 32];
    const float* Qb = g_Q + (size_t)b * NN * OO;

    float m1 = -FLT_MAX, m2 = -FLT_MAX;
    #pragma unroll
    for (int kk = 0; kk < KNB; ++kk) {
        int nid = __shfl_sync(FULLMASK, li, kk);
        const float* Qr = Qb + (size_t)nid * OO;
        float y1 = (p1 + __ldg(&Qr[lane]))      * sc1 + bi1;
        float y2 = (p2 + __ldg(&Qr[lane + 32])) * sc2 + bi2;
        y1 = (y1 >= 0.f) ? y1 : 0.2f * y1;
        y2 = (y2 >= 0.f) ? y2 : 0.2f * y2;
        m1 = fmaxf(m1, y1);
        m2 = fmaxf(m2, y2);
    }
    out[((size_t)b * OO + lane)      * NN + n] = m1;
    out[((size_t)b * OO + lane + 32) * NN + n] = m2;
}

// ---------------------------------------------------------------------------
extern "C" void kernel_launch(void* const* d_in, const int* in_sizes, int n_in,
                              void* d_out, int out_size) {
    const float* x     = (const float*)d_in[0];
    const float* W     = (const float*)d_in[1];
    const float* gamma = (const float*)d_in[2];
    const float* beta  = (const float*)d_in[3];
    const float* rmean = (const float*)d_in[4];
    const float* rvar  = (const float*)d_in[5];
    float* out = (float*)d_out;

    sq_kernel<<<128, 256>>>(x);
    pq_kernel<<<8192, 256>>>(x, W);
    {
        dim3 grid(NN / 128, NN / 128, BB);
        pd_gemm_sym<<<grid, 256>>>(x);
    }
    topk_fused<<<4096, 256>>>(gamma, beta, rmean, rvar, out);
}